// round 14
// baseline (speedup 1.0000x reference)
#include <cuda_runtime.h>
#include <cstddef>

// Problem constants (fixed shapes)
#define N_ROWS 14400      // bs*Q = 16*900
#define N_CLS  91
#define N_TGT  4096
#define T_OUT  4096

#define TPB        128
#define TGT_PER_TH 4                    // two packed f32x2 lane-pairs
#define TILE_T     (TPB * TGT_PER_TH)   // 512 targets per block
#define TILE_R     64                   // rows per block

// Scratch (no allocations allowed in kernel_launch)
__device__ float g_cc[N_ROWS * N_CLS];   // 2*(pos-neg) + 2, 5.24 MB

// ---------------------------------------------------------------------------
// Packed f32x2 helpers (sm_100+: add/mul/fma.rn.f32x2)
// ---------------------------------------------------------------------------
struct F2 { unsigned long long u; };

__device__ __forceinline__ F2 pack2(float lo, float hi) {
    F2 r; asm("mov.b64 %0, {%1, %2};" : "=l"(r.u) : "f"(lo), "f"(hi)); return r;
}
__device__ __forceinline__ void unpack2(F2 a, float& lo, float& hi) {
    asm("mov.b64 {%0, %1}, %2;" : "=f"(lo), "=f"(hi) : "l"(a.u));
}
__device__ __forceinline__ F2 add2(F2 a, F2 b) {
    F2 r; asm("add.rn.f32x2 %0, %1, %2;" : "=l"(r.u) : "l"(a.u), "l"(b.u)); return r;
}
__device__ __forceinline__ F2 mul2(F2 a, F2 b) {
    F2 r; asm("mul.rn.f32x2 %0, %1, %2;" : "=l"(r.u) : "l"(a.u), "l"(b.u)); return r;
}
__device__ __forceinline__ F2 fma2(F2 a, F2 b, F2 c) {
    F2 r; asm("fma.rn.f32x2 %0, %1, %2, %3;"
              : "=l"(r.u) : "l"(a.u), "l"(b.u), "l"(c.u)); return r;
}
__device__ __forceinline__ F2 abs2(F2 a, F2 mask) {   // packed |x| via AND (alu pipe)
    F2 r; asm("and.b64 %0, %1, %2;" : "=l"(r.u) : "l"(a.u), "l"(mask.u)); return r;
}
__device__ __forceinline__ float rcp_fast(float x) {
    float r; asm("rcp.approx.f32 %0, %1;" : "=f"(r) : "f"(x)); return r;
}
// min(-|a|, -|b|)  (one FMNMX with neg-abs source modifiers)
__device__ __forceinline__ float minnegabs(float a, float b) {
    return fminf(-fabsf(a), -fabsf(b));
}

// ---------------------------------------------------------------------------
// Prep: class-cost table only (pre-scaled: 2*(pos-neg)+2, fast intrinsics).
// Vectorized: 4 elements per thread. 1310400 elems = 327600 float4.
// ---------------------------------------------------------------------------
__global__ void prep_kernel(const float* __restrict__ logits) {
    int i = blockIdx.x * blockDim.x + threadIdx.x;
    if (i >= (N_ROWS * N_CLS) / 4) return;
    float4 x4 = ((const float4*)logits)[i];
    float4 o4;
    #pragma unroll
    for (int k = 0; k < 4; ++k) {
        float x = ((const float*)&x4)[k];
        float p = rcp_fast(1.0f + __expf(-x));
        float om = 1.0f - p;
        float pos = 0.25f * om * om * (-__logf(p  + 1e-8f));
        float neg = 0.75f * p  * p  * (-__logf(om + 1e-8f));
        ((float*)&o4)[k] = 2.0f * (pos - neg) + 2.0f;
    }
    ((float4*)g_cc)[i] = o4;
}

// Per-packed-pair target constants (half-width form)
struct TgtPair {
    F2 TCXN, TCYN;    // {-tcx0,-tcx1}, {-tcy0,-tcy1}
    F2 SWTN, SHTN;    // {-tw0/2,-tw1/2}, {-th0/2,-th1/2}
    F2 TA2;           // {tw0*th0, tw1*th1}
    int o0, o1;       // class offsets into cc row
};

// Packed cost (2 targets) for one row. Half-width identities:
//   m  = max(|d|, |hd|);  iwu = hs - m;  ew = hs + m
__device__ __forceinline__ F2 pair_cost(
    const TgtPair& T, F2 CX, F2 CY, F2 SW, F2 SH, F2 AR2,
    F2 NEG1, F2 NEG2, F2 TWO2, F2 FIVE2, F2 MASK,
    const float* __restrict__ ccrow)
{
    F2 Dx  = add2(CX, T.TCXN);           // c - tc
    F2 Dy  = add2(CY, T.TCYN);
    F2 HDx = add2(SW, T.SWTN);           // s - st
    F2 HDy = add2(SH, T.SHTN);
    F2 HSx = fma2(T.SWTN, NEG1, SW);     // s + st
    F2 HSy = fma2(T.SHTN, NEG1, SH);

    // L1 via packed abs (LOP3, alu pipe): ab = (|dx|+|dy|) + 2*(|hdx|+|hdy|)
    F2 T2  = add2(abs2(Dx, MASK), abs2(Dy, MASK));
    F2 U2  = add2(abs2(HDx, MASK), abs2(HDy, MASK));
    F2 AB2 = fma2(U2, TWO2, T2);

    float dx0, dx1, dy0, dy1, hdx0, hdx1, hdy0, hdy1;
    unpack2(Dx, dx0, dx1);   unpack2(Dy, dy0, dy1);
    unpack2(HDx, hdx0, hdx1); unpack2(HDy, hdy0, hdy1);

    // mn = -max(|d|,|hd|) per axis per target (FMNMX, neg-abs mods)
    float mnx0 = minnegabs(dx0, hdx0), mnx1 = minnegabs(dx1, hdx1);
    float mny0 = minnegabs(dy0, hdy0), mny1 = minnegabs(dy1, hdy1);

    // clamped intersection sides: iw = sat(hs + mn)  (hs <= 1, mn <= 0)
    float hsx0, hsx1, hsy0, hsy1;
    unpack2(HSx, hsx0, hsx1); unpack2(HSy, hsy0, hsy1);
    float iw0 = __saturatef(hsx0 + mnx0), iw1 = __saturatef(hsx1 + mnx1);
    float ih0 = __saturatef(hsy0 + mny0), ih1 = __saturatef(hsy1 + mny1);
    F2 IW = pack2(iw0, iw1);
    F2 IH = pack2(ih0, ih1);
    F2 MNX = pack2(mnx0, mnx1);
    F2 MNY = pack2(mny0, mny1);

    F2 EW = fma2(MNX, NEG1, HSx);        // hs + m
    F2 EH = fma2(MNY, NEG1, HSy);

    F2 ARTA  = add2(AR2, T.TA2);         // ar + tw*th
    F2 INTER = mul2(IW, IH);
    F2 UNI   = fma2(INTER, NEG1, ARTA);  // union
    F2 AE    = mul2(EW, EH);

    // shared rcp: rp = rcp(d0*d1); 1/d0 = rp*d1 ; 1/d1 = rp*d0
    F2 DEN = mul2(UNI, AE);
    float d0, d1;
    unpack2(DEN, d0, d1);
    float rp = rcp_fast(d0 * d1);        // ONE MUFU per packed pair
    F2 RP2 = pack2(rp, rp);
    F2 DSW = pack2(d1, d0);
    F2 NUM = fma2(UNI, UNI, mul2(INTER, AE));
    F2 S   = mul2(NUM, mul2(RP2, DSW));  // inter/uni + uni/ae

    F2 CCV = pack2(ccrow[T.o0], ccrow[T.o1]);   // 2cc+2
    F2 C   = fma2(S, NEG2, CCV);                // ccv - 2s
    // cost = 5*ab + C
    return fma2(AB2, FIVE2, C);
}

// ---------------------------------------------------------------------------
// Main: block = 512 targets x 64 rows. 128 threads, 4 targets/thread as two
// independent packed lanes. Half-width algebra, L1 sums on the alu pipe.
// ---------------------------------------------------------------------------
__global__ void __launch_bounds__(TPB)
cost_kernel_main(const float* __restrict__ pboxes,
                 const float* __restrict__ tboxes,
                 const int*   __restrict__ tids,
                 float*       __restrict__ out)
{
    __shared__ ulonglong2 s_rc[TILE_R];              // {cx,cx},{cy,cy}
    __shared__ ulonglong2 s_rs[TILE_R];              // {w/2,w/2},{h/2,h/2}
    __shared__ unsigned long long s_rar[TILE_R];     // {w*h, w*h}
    __shared__ float s_cc[TILE_R * N_CLS];           // row-major cc tile

    const int n0 = blockIdx.y * TILE_R;
    const int t0 = blockIdx.x * TILE_T + threadIdx.x * TGT_PER_TH;

    // Stage row records (thread t < 64 handles row t)
    if (threadIdx.x < TILE_R) {
        int n = n0 + threadIdx.x;
        float4 p = ((const float4*)pboxes)[n];
        ulonglong2 rc, rs;
        rc.x = pack2(p.x, p.x).u;                    // cx
        rc.y = pack2(p.y, p.y).u;                    // cy
        rs.x = pack2(0.5f * p.z, 0.5f * p.z).u;      // w/2
        rs.y = pack2(0.5f * p.w, 0.5f * p.w).u;      // h/2
        s_rc[threadIdx.x] = rc;
        s_rs[threadIdx.x] = rs;
        s_rar[threadIdx.x] = pack2(p.z * p.w, p.z * p.w).u;
    }

    // Stage cc tile (contiguous float4 copy; 1456 float4, 16B-aligned)
    {
        const float4* __restrict__ src = (const float4*)(g_cc + n0 * N_CLS);
        float4* __restrict__ dst = (float4*)s_cc;
        #pragma unroll
        for (int q = 0; q < 12; ++q) {
            int idx = q * TPB + threadIdx.x;
            if (idx < (TILE_R * N_CLS) / 4) dst[idx] = src[idx];
        }
    }

    // Target state: 4 targets as two packed pairs
    TgtPair A, B;
    {
        const float4 ca = ((const float4*)tboxes)[t0];
        const float4 cb = ((const float4*)tboxes)[t0 + 1];
        const float4 cc = ((const float4*)tboxes)[t0 + 2];
        const float4 cd = ((const float4*)tboxes)[t0 + 3];
        A.TCXN = pack2(-ca.x, -cb.x);
        A.TCYN = pack2(-ca.y, -cb.y);
        A.SWTN = pack2(-0.5f * ca.z, -0.5f * cb.z);
        A.SHTN = pack2(-0.5f * ca.w, -0.5f * cb.w);
        A.TA2  = pack2(ca.z * ca.w, cb.z * cb.w);
        B.TCXN = pack2(-cc.x, -cd.x);
        B.TCYN = pack2(-cc.y, -cd.y);
        B.SWTN = pack2(-0.5f * cc.z, -0.5f * cd.z);
        B.SHTN = pack2(-0.5f * cc.w, -0.5f * cd.w);
        B.TA2  = pack2(cc.z * cc.w, cd.z * cd.w);
        A.o0 = tids[t0];     A.o1 = tids[t0 + 1];
        B.o0 = tids[t0 + 2]; B.o1 = tids[t0 + 3];
    }

    const F2 NEG1  = pack2(-1.0f, -1.0f);
    const F2 NEG2  = pack2(-2.0f, -2.0f);
    const F2 TWO2  = pack2(2.0f, 2.0f);
    const F2 FIVE2 = pack2(5.0f, 5.0f);
    F2 MASK; MASK.u = 0x7FFFFFFF7FFFFFFFULL;

    __syncthreads();

    float* __restrict__ outp = out + (size_t)n0 * T_OUT + t0;

    #pragma unroll 4
    for (int r = 0; r < TILE_R; ++r) {
        const ulonglong2 rc = s_rc[r];
        const ulonglong2 rs = s_rs[r];
        const F2 CX = { rc.x }, CY = { rc.y };
        const F2 SW = { rs.x }, SH = { rs.y };
        const F2 AR2 = { s_rar[r] };
        const float* __restrict__ ccrow = s_cc + r * N_CLS;

        F2 cA = pair_cost(A, CX, CY, SW, SH, AR2,
                          NEG1, NEG2, TWO2, FIVE2, MASK, ccrow);
        F2 cB = pair_cost(B, CX, CY, SW, SH, AR2,
                          NEG1, NEG2, TWO2, FIVE2, MASK, ccrow);

        float ca0, ca1, cb0, cb1;
        unpack2(cA, ca0, ca1);
        unpack2(cB, cb0, cb1);
        *(float4*)(outp + (size_t)r * T_OUT) = make_float4(ca0, ca1, cb0, cb1);
    }
}

// ---------------------------------------------------------------------------
// Launch
// ---------------------------------------------------------------------------
extern "C" void kernel_launch(void* const* d_in, const int* in_sizes, int n_in,
                              void* d_out, int out_size) {
    const float* logits = (const float*)d_in[0];   // [16,900,91]
    const float* pboxes = (const float*)d_in[1];   // [16,900,4]
    const int*   tids   = (const int*)  d_in[2];   // [4096]
    const float* tboxes = (const float*)d_in[3];   // [4096,4]
    float*       out    = (float*)d_out;           // [16,900,4096]

    {
        int total = (N_ROWS * N_CLS) / 4;          // vectorized prep
        prep_kernel<<<(total + 255) / 256, 256>>>(logits);
    }
    {
        dim3 grid(T_OUT / TILE_T, N_ROWS / TILE_R);
        cost_kernel_main<<<grid, TPB>>>(pboxes, tboxes, tids, out);
    }
}

// round 15
// speedup vs baseline: 1.0490x; 1.0490x over previous
#include <cuda_runtime.h>
#include <cstddef>

// Problem constants (fixed shapes)
#define N_ROWS 14400      // bs*Q = 16*900
#define N_CLS  91
#define N_TGT  4096
#define T_OUT  4096

#define TPB        128
#define TGT_PER_TH 4                    // two packed f32x2 lane-pairs
#define TILE_T     (TPB * TGT_PER_TH)   // 512 targets per block
#define TILE_R     32                   // rows per block

// Scratch (no allocations allowed in kernel_launch)
__device__ float g_cc[N_ROWS * N_CLS];   // 2*(pos-neg) + 2, 5.24 MB

// ---------------------------------------------------------------------------
// Packed f32x2 helpers (sm_100+: add/mul/fma.rn.f32x2)
// ---------------------------------------------------------------------------
struct F2 { unsigned long long u; };

__device__ __forceinline__ F2 pack2(float lo, float hi) {
    F2 r; asm("mov.b64 %0, {%1, %2};" : "=l"(r.u) : "f"(lo), "f"(hi)); return r;
}
__device__ __forceinline__ void unpack2(F2 a, float& lo, float& hi) {
    asm("mov.b64 {%0, %1}, %2;" : "=f"(lo), "=f"(hi) : "l"(a.u));
}
__device__ __forceinline__ F2 add2(F2 a, F2 b) {
    F2 r; asm("add.rn.f32x2 %0, %1, %2;" : "=l"(r.u) : "l"(a.u), "l"(b.u)); return r;
}
__device__ __forceinline__ F2 mul2(F2 a, F2 b) {
    F2 r; asm("mul.rn.f32x2 %0, %1, %2;" : "=l"(r.u) : "l"(a.u), "l"(b.u)); return r;
}
__device__ __forceinline__ F2 fma2(F2 a, F2 b, F2 c) {
    F2 r; asm("fma.rn.f32x2 %0, %1, %2, %3;"
              : "=l"(r.u) : "l"(a.u), "l"(b.u), "l"(c.u)); return r;
}
__device__ __forceinline__ float rcp_fast(float x) {
    float r; asm("rcp.approx.f32 %0, %1;" : "=f"(r) : "f"(x)); return r;
}
// min(-|a|, -|b|)  (one FMNMX with neg-abs source modifiers)
__device__ __forceinline__ float minnegabs(float a, float b) {
    return fminf(-fabsf(a), -fabsf(b));
}

// ---------------------------------------------------------------------------
// Prep: class-cost table only (pre-scaled: 2*(pos-neg)+2, fast intrinsics).
// Vectorized: 4 elements per thread via float4 (coalesced 16B accesses).
// ---------------------------------------------------------------------------
__global__ void prep_kernel(const float* __restrict__ logits) {
    int i = blockIdx.x * blockDim.x + threadIdx.x;
    if (i >= (N_ROWS * N_CLS) / 4) return;
    float4 x4 = ((const float4*)logits)[i];
    float4 o4;
    #pragma unroll
    for (int k = 0; k < 4; ++k) {
        float x = ((const float*)&x4)[k];
        float p = rcp_fast(1.0f + __expf(-x));
        float om = 1.0f - p;
        float pos = 0.25f * om * om * (-__logf(p  + 1e-8f));
        float neg = 0.75f * p  * p  * (-__logf(om + 1e-8f));
        ((float*)&o4)[k] = 2.0f * (pos - neg) + 2.0f;
    }
    ((float4*)g_cc)[i] = o4;
}

// Per-packed-pair target constants (half-width form)
struct TgtPair {
    F2 TCXN, TCYN;    // {-tcx0,-tcx1}, {-tcy0,-tcy1}
    F2 SWTN, SHTN;    // {-tw0/2,-tw1/2}, {-th0/2,-th1/2}
    F2 TA2;           // {tw0*th0, tw1*th1}
    int o0, o1;       // class offsets into cc row
};

// Packed cost (2 targets) for one row. Half-width identities:
//   m  = max(|d|, |hd|);  iwu = hs - m;  ew = hs + m
// with hs = s + st, hd = s - st, d = c - tc (per axis).
__device__ __forceinline__ F2 pair_cost(
    const TgtPair& T, F2 CX, F2 CY, F2 SW, F2 SH, F2 AR2,
    F2 NEG1, F2 NEG2, F2 FIVE2, F2 TEN2, const float* __restrict__ ccrow)
{
    F2 Dx  = add2(CX, T.TCXN);           // c - tc
    F2 Dy  = add2(CY, T.TCYN);
    F2 HDx = add2(SW, T.SWTN);           // s - st
    F2 HDy = add2(SH, T.SHTN);
    F2 HSx = fma2(T.SWTN, NEG1, SW);     // s + st
    F2 HSy = fma2(T.SHTN, NEG1, SH);

    float dx0, dx1, dy0, dy1, hdx0, hdx1, hdy0, hdy1;
    unpack2(Dx, dx0, dx1);   unpack2(Dy, dy0, dy1);
    unpack2(HDx, hdx0, hdx1); unpack2(HDy, hdy0, hdy1);

    // mn = -max(|d|,|hd|) per axis per target (FMNMX, neg-abs mods)
    float mnx0 = minnegabs(dx0, hdx0), mnx1 = minnegabs(dx1, hdx1);
    float mny0 = minnegabs(dy0, hdy0), mny1 = minnegabs(dy1, hdy1);

    // L1 pieces: a = |dx|+|dy|, b = |hdx|+|hdy| (|w-tw| = 2|hd|)
    float a0 = fabsf(dx0) + fabsf(dy0), a1 = fabsf(dx1) + fabsf(dy1);
    float b0 = fabsf(hdx0) + fabsf(hdy0), b1 = fabsf(hdx1) + fabsf(hdy1);
    F2 A2 = pack2(a0, a1);
    F2 B2 = pack2(b0, b1);

    // clamped intersection sides: iw = sat(hs + mn)  (hs <= 1, mn <= 0)
    float hsx0, hsx1, hsy0, hsy1;
    unpack2(HSx, hsx0, hsx1); unpack2(HSy, hsy0, hsy1);
    float iw0 = __saturatef(hsx0 + mnx0), iw1 = __saturatef(hsx1 + mnx1);
    float ih0 = __saturatef(hsy0 + mny0), ih1 = __saturatef(hsy1 + mny1);
    F2 IW = pack2(iw0, iw1);
    F2 IH = pack2(ih0, ih1);
    F2 MNX = pack2(mnx0, mnx1);
    F2 MNY = pack2(mny0, mny1);

    F2 EW = fma2(MNX, NEG1, HSx);        // hs + m
    F2 EH = fma2(MNY, NEG1, HSy);

    F2 ARTA  = add2(AR2, T.TA2);         // ar + tw*th
    F2 INTER = mul2(IW, IH);
    F2 UNI   = fma2(INTER, NEG1, ARTA);  // union
    F2 AE    = mul2(EW, EH);

    // shared rcp: rp = rcp(d0*d1); 1/d0 = rp*d1 ; 1/d1 = rp*d0
    F2 DEN = mul2(UNI, AE);
    float d0, d1;
    unpack2(DEN, d0, d1);
    float rp = rcp_fast(d0 * d1);        // ONE MUFU per packed pair
    F2 RP2 = pack2(rp, rp);
    F2 DSW = pack2(d1, d0);
    F2 NUM = fma2(UNI, UNI, mul2(INTER, AE));
    F2 S   = mul2(NUM, mul2(RP2, DSW));  // inter/uni + uni/ae

    F2 CCV = pack2(ccrow[T.o0], ccrow[T.o1]);   // 2cc+2
    F2 C   = fma2(S, NEG2, CCV);                // ccv - 2s
    // cost = 5*a + 10*b + C
    return fma2(A2, FIVE2, fma2(B2, TEN2, C));
}

// ---------------------------------------------------------------------------
// Main: block = 512 targets x 32 rows. 128 threads, 4 targets/thread as two
// independent packed lanes. Half-width algebra: no xyxy anywhere.
// (R13 configuration — best measured main kernel: 60.6us)
// ---------------------------------------------------------------------------
__global__ void __launch_bounds__(TPB)
cost_kernel_main(const float* __restrict__ pboxes,
                 const float* __restrict__ tboxes,
                 const int*   __restrict__ tids,
                 float*       __restrict__ out)
{
    __shared__ ulonglong2 s_rc[TILE_R];              // {cx,cx},{cy,cy}
    __shared__ ulonglong2 s_rs[TILE_R];              // {w/2,w/2},{h/2,h/2}
    __shared__ unsigned long long s_rar[TILE_R];     // {w*h, w*h}
    __shared__ float s_cc[TILE_R * N_CLS];           // row-major cc tile

    const int n0 = blockIdx.y * TILE_R;
    const int t0 = blockIdx.x * TILE_T + threadIdx.x * TGT_PER_TH;

    // Stage row records (thread t < 32 handles row t)
    if (threadIdx.x < TILE_R) {
        int n = n0 + threadIdx.x;
        float4 p = ((const float4*)pboxes)[n];
        ulonglong2 rc, rs;
        rc.x = pack2(p.x, p.x).u;                    // cx
        rc.y = pack2(p.y, p.y).u;                    // cy
        rs.x = pack2(0.5f * p.z, 0.5f * p.z).u;      // w/2
        rs.y = pack2(0.5f * p.w, 0.5f * p.w).u;      // h/2
        s_rc[threadIdx.x] = rc;
        s_rs[threadIdx.x] = rs;
        s_rar[threadIdx.x] = pack2(p.z * p.w, p.z * p.w).u;
    }

    // Stage cc tile (contiguous float4 copy; 728 float4, 16B-aligned)
    {
        const float4* __restrict__ src = (const float4*)(g_cc + n0 * N_CLS);
        float4* __restrict__ dst = (float4*)s_cc;
        #pragma unroll
        for (int q = 0; q < 6; ++q) {
            int idx = q * TPB + threadIdx.x;
            if (idx < (TILE_R * N_CLS) / 4) dst[idx] = src[idx];
        }
    }

    // Target state: 4 targets as two packed pairs
    TgtPair A, B;
    {
        const float4 ca = ((const float4*)tboxes)[t0];
        const float4 cb = ((const float4*)tboxes)[t0 + 1];
        const float4 cc = ((const float4*)tboxes)[t0 + 2];
        const float4 cd = ((const float4*)tboxes)[t0 + 3];
        A.TCXN = pack2(-ca.x, -cb.x);
        A.TCYN = pack2(-ca.y, -cb.y);
        A.SWTN = pack2(-0.5f * ca.z, -0.5f * cb.z);
        A.SHTN = pack2(-0.5f * ca.w, -0.5f * cb.w);
        A.TA2  = pack2(ca.z * ca.w, cb.z * cb.w);
        B.TCXN = pack2(-cc.x, -cd.x);
        B.TCYN = pack2(-cc.y, -cd.y);
        B.SWTN = pack2(-0.5f * cc.z, -0.5f * cd.z);
        B.SHTN = pack2(-0.5f * cc.w, -0.5f * cd.w);
        B.TA2  = pack2(cc.z * cc.w, cd.z * cd.w);
        A.o0 = tids[t0];     A.o1 = tids[t0 + 1];
        B.o0 = tids[t0 + 2]; B.o1 = tids[t0 + 3];
    }

    const F2 NEG1  = pack2(-1.0f, -1.0f);
    const F2 NEG2  = pack2(-2.0f, -2.0f);
    const F2 FIVE2 = pack2(5.0f, 5.0f);
    const F2 TEN2  = pack2(10.0f, 10.0f);

    __syncthreads();

    float* __restrict__ outp = out + (size_t)n0 * T_OUT + t0;

    #pragma unroll 4
    for (int r = 0; r < TILE_R; ++r) {
        const ulonglong2 rc = s_rc[r];
        const ulonglong2 rs = s_rs[r];
        const F2 CX = { rc.x }, CY = { rc.y };
        const F2 SW = { rs.x }, SH = { rs.y };
        const F2 AR2 = { s_rar[r] };
        const float* __restrict__ ccrow = s_cc + r * N_CLS;

        F2 cA = pair_cost(A, CX, CY, SW, SH, AR2, NEG1, NEG2, FIVE2, TEN2, ccrow);
        F2 cB = pair_cost(B, CX, CY, SW, SH, AR2, NEG1, NEG2, FIVE2, TEN2, ccrow);

        float ca0, ca1, cb0, cb1;
        unpack2(cA, ca0, ca1);
        unpack2(cB, cb0, cb1);
        *(float4*)(outp + (size_t)r * T_OUT) = make_float4(ca0, ca1, cb0, cb1);
    }
}

// ---------------------------------------------------------------------------
// Launch
// ---------------------------------------------------------------------------
extern "C" void kernel_launch(void* const* d_in, const int* in_sizes, int n_in,
                              void* d_out, int out_size) {
    const float* logits = (const float*)d_in[0];   // [16,900,91]
    const float* pboxes = (const float*)d_in[1];   // [16,900,4]
    const int*   tids   = (const int*)  d_in[2];   // [4096]
    const float* tboxes = (const float*)d_in[3];   // [4096,4]
    float*       out    = (float*)d_out;           // [16,900,4096]

    {
        int total = (N_ROWS * N_CLS) / 4;          // vectorized prep
        prep_kernel<<<(total + 255) / 256, 256>>>(logits);
    }
    {
        dim3 grid(T_OUT / TILE_T, N_ROWS / TILE_R);
        cost_kernel_main<<<grid, TPB>>>(pboxes, tboxes, tids, out);
    }
}